// round 15
// baseline (speedup 1.0000x reference)
#include <cuda_runtime.h>
#include <cstdint>

#define BSZ 8
#define SEQ 16
#define DIM 4096
#define NH 32
#define NKV 8
#define HD 128
#define CL 4096
#define NT (BSZ*SEQ)                 // 128 tokens
#define NQKV (DIM + 2*NKV*HD)        // 6144
#define ROPE_LIM (DIM + NKV*HD)      // 5120
#define CACHE_ELEMS (BSZ*CL*NKV*HD)
#define CK_OFF ((size_t)NT*DIM)
#define CV_OFF (CK_OFF + CACHE_ELEMS)
#define RSQRT_HD 0.08838834764831845f
#define NSPLIT 8
#define KEYS_PER_SPLIT (CL/NSPLIT)   // 512

typedef unsigned long long ull;

__device__ float    g_qkv[(size_t)NT*NQKV];
__device__ float    g_po[(size_t)BSZ*NKV*NSPLIT*64*128];
__device__ float    g_pml[(size_t)BSZ*NKV*NSPLIT*64*2];
__device__ float    g_pc[(size_t)2*NT*DIM];       // WO split-K partials
__device__ uint16_t g_xhi[(size_t)NT*DIM];
__device__ uint16_t g_xlo[(size_t)NT*DIM];
__device__ uint16_t g_ahi[(size_t)NT*DIM];
__device__ uint16_t g_alo[(size_t)NT*DIM];

// ---- bf16 mma.sync (baseline sm_80+ ISA) ----------------------------------
#define MMA_BF16(d, a0,a1,a2,a3, b0,b1) \
    asm volatile( \
        "mma.sync.aligned.m16n8k16.row.col.f32.bf16.bf16.f32 " \
        "{%0,%1,%2,%3}, {%4,%5,%6,%7}, {%8,%9}, {%0,%1,%2,%3};" \
        : "+f"(d[0]), "+f"(d[1]), "+f"(d[2]), "+f"(d[3]) \
        : "r"(a0), "r"(a1), "r"(a2), "r"(a3), "r"(b0), "r"(b1))

__device__ __forceinline__ void ldmx4t(uint32_t& r0, uint32_t& r1,
                                       uint32_t& r2, uint32_t& r3, uint32_t addr) {
    asm volatile("ldmatrix.sync.aligned.m8n8.x4.trans.shared.b16 {%0,%1,%2,%3}, [%4];"
        : "=r"(r0), "=r"(r1), "=r"(r2), "=r"(r3) : "r"(addr));
}
__device__ __forceinline__ uint32_t smem_u32(const void* p) {
    uint32_t a;
    asm("{ .reg .u64 t; cvta.to.shared.u64 t, %1; cvt.u32.u64 %0, t; }"
        : "=r"(a) : "l"(p));
    return a;
}
__device__ __forceinline__ void cpasync16(uint32_t dst, const void* src) {
    asm volatile("cp.async.cg.shared.global [%0], [%1], 16;"
                 :: "r"(dst), "l"(src) : "memory");
}
#define CP_COMMIT() asm volatile("cp.async.commit_group;" ::: "memory")
#define CP_WAIT0()  asm volatile("cp.async.wait_group 0;" ::: "memory")

// split one float pair -> (hi bf16x2, lo bf16x2); first element in low half
__device__ __forceinline__ void split2(float x, float y, uint32_t& hi, uint32_t& lo) {
    uint32_t ux = __float_as_uint(x), uy = __float_as_uint(y);
    float hx = __uint_as_float(ux & 0xFFFF0000u);
    float hy = __uint_as_float(uy & 0xFFFF0000u);
    hi = __byte_perm(ux, uy, 0x7632);
    lo = __byte_perm(__float_as_uint(x - hx), __float_as_uint(y - hy), 0x7632);
}

// ---------------------------------------------------------------------------
// convert_x: split fp32 x into hi/lo bf16 planes.
// ---------------------------------------------------------------------------
__global__ __launch_bounds__(256) void convert_x(
    const float* __restrict__ x, uint16_t* __restrict__ xhi, uint16_t* __restrict__ xlo)
{
    int i = blockIdx.x * 256 + threadIdx.x;       // float4 index, 131072 total
    float4 v = ((const float4*)x)[i];
    uint32_t h0, l0, h1, l1;
    split2(v.x, v.y, h0, l0);
    split2(v.z, v.w, h1, l1);
    uint2 hi = {h0, h1}, lo = {l0, l1};
    ((uint2*)xhi)[i] = hi;
    ((uint2*)xlo)[i] = lo;
}

// ---------------------------------------------------------------------------
// Tensor-core GEMM: A pre-split bf16 (synchronous uint4 prefetch — same
// skeleton as the measured-good fp32 version), W fp32 split in-kernel.
// Optional split-K via gridDim.y (partials at C + ks*NT*ldc).
// ---------------------------------------------------------------------------
#define BKS 64
#define ASTR 72
#define U16_AHI 0
#define U16_ALO (128*ASTR)
#define U16_WHI (2*128*ASTR)

template<int BN>
__global__ __launch_bounds__(256) void gemm_mma(
    const uint16_t* __restrict__ Ahi, const uint16_t* __restrict__ Alo,
    const float* __restrict__ W0, const float* __restrict__ W1,
    const float* __restrict__ W2,
    float* __restrict__ C, int ldc,
    const float* __restrict__ freqs, int ropeLim)
{
    extern __shared__ char smraw[];
    uint16_t* sm16 = (uint16_t*)smraw;
    constexpr int MH = BN / 32;
    constexpr int WLO = 2*128*ASTR + BN*ASTR;

    const int t    = threadIdx.x;
    const int wid  = t >> 5;
    const int lane = t & 31;
    const int g    = lane >> 2;
    const int tg   = lane & 3;
    const int wm   = (BN == 64) ? (wid >> 1) : wid;
    const int wn   = (BN == 64) ? (wid & 1) : 0;
    const int n0   = blockIdx.x * BN;
    const int ks   = blockIdx.y;
    const int kbase = ks * (DIM / gridDim.y);
    const int nstg  = DIM / gridDim.y / BKS;

    const float* W = W0; int nr = n0;
    if (W1 != nullptr && n0 >= DIM) {
        if (n0 < DIM + NKV*HD) { W = W1; nr = n0 - DIM; }
        else                   { W = W2; nr = n0 - DIM - NKV*HD; }
    }

    float acc[MH][4][4] = {};
    uint4 pah[4], pal[4];
    float4 pw[BN/16];

    // prefetch stage 0: A as pre-split bf16 (uint4 = 8 u16), W as fp32
    #pragma unroll
    for (int it = 0; it < 4; it++) {
        int idx = t + it*256;               // 1024: 128 rows x 8 chunks
        int row = idx >> 3, c = idx & 7;
        pah[it] = *(const uint4*)(Ahi + (size_t)row*DIM + kbase + c*8);
        pal[it] = *(const uint4*)(Alo + (size_t)row*DIM + kbase + c*8);
    }
    #pragma unroll
    for (int it = 0; it < BN/16; it++) {
        int v = t + it*256, row = v >> 4, gq = v & 15;
        pw[it] = *(const float4*)(W + (size_t)(nr + row) * DIM + kbase + gq*4);
    }

    for (int st = 0; st < nstg; st++) {
        __syncthreads();
        // store A tiles (no conversion)
        #pragma unroll
        for (int it = 0; it < 4; it++) {
            int idx = t + it*256;
            int row = idx >> 3, c = idx & 7;
            int o = row*ASTR + c*8;
            *(uint4*)&sm16[U16_AHI + o] = pah[it];
            *(uint4*)&sm16[U16_ALO + o] = pal[it];
        }
        // store W conversion
        #pragma unroll
        for (int it = 0; it < BN/16; it++) {
            int v = t + it*256, row = v >> 4, gq = v & 15;
            int idx = row*ASTR + gq*4;
            uint32_t h0, l0, h1, l1;
            split2(pw[it].x, pw[it].y, h0, l0);
            split2(pw[it].z, pw[it].w, h1, l1);
            *(uint32_t*)&sm16[U16_WHI + idx]     = h0;
            *(uint32_t*)&sm16[U16_WHI + idx + 2] = h1;
            *(uint32_t*)&sm16[WLO + idx]     = l0;
            *(uint32_t*)&sm16[WLO + idx + 2] = l1;
        }
        __syncthreads();

        if (st + 1 < nstg) {
            const int k0 = kbase + (st + 1) * BKS;
            #pragma unroll
            for (int it = 0; it < 4; it++) {
                int idx = t + it*256;
                int row = idx >> 3, c = idx & 7;
                pah[it] = *(const uint4*)(Ahi + (size_t)row*DIM + k0 + c*8);
                pal[it] = *(const uint4*)(Alo + (size_t)row*DIM + k0 + c*8);
            }
            #pragma unroll
            for (int it = 0; it < BN/16; it++) {
                int v = t + it*256, row = v >> 4, gq = v & 15;
                pw[it] = *(const float4*)(W + (size_t)(nr + row) * DIM + k0 + gq*4);
            }
        }

        #pragma unroll
        for (int kk = 0; kk < 4; kk++) {
            const int kb = kk*16 + 2*tg;
            uint32_t bh0[4], bh1[4], bl0[4], bl1[4];
            #pragma unroll
            for (int nt = 0; nt < 4; nt++) {
                int bi = (wn*32 + nt*8 + g)*ASTR + kb;
                bh0[nt] = *(const uint32_t*)&sm16[U16_WHI + bi];
                bh1[nt] = *(const uint32_t*)&sm16[U16_WHI + bi + 8];
                bl0[nt] = *(const uint32_t*)&sm16[WLO + bi];
                bl1[nt] = *(const uint32_t*)&sm16[WLO + bi + 8];
            }
            #pragma unroll
            for (int mh = 0; mh < MH; mh++) {
                int ai = (wm*16*MH + mh*16 + g)*ASTR + kb;
                uint32_t ah0 = *(const uint32_t*)&sm16[U16_AHI + ai];
                uint32_t ah1 = *(const uint32_t*)&sm16[U16_AHI + ai + 8*ASTR];
                uint32_t ah2 = *(const uint32_t*)&sm16[U16_AHI + ai + 8];
                uint32_t ah3 = *(const uint32_t*)&sm16[U16_AHI + ai + 8*ASTR + 8];
                uint32_t al0 = *(const uint32_t*)&sm16[U16_ALO + ai];
                uint32_t al1 = *(const uint32_t*)&sm16[U16_ALO + ai + 8*ASTR];
                uint32_t al2 = *(const uint32_t*)&sm16[U16_ALO + ai + 8];
                uint32_t al3 = *(const uint32_t*)&sm16[U16_ALO + ai + 8*ASTR + 8];
                #pragma unroll
                for (int nt = 0; nt < 4; nt++) {
                    MMA_BF16(acc[mh][nt], ah0, ah1, ah2, ah3, bh0[nt], bh1[nt]);
                    MMA_BF16(acc[mh][nt], ah0, ah1, ah2, ah3, bl0[nt], bl1[nt]);
                    MMA_BF16(acc[mh][nt], al0, al1, al2, al3, bh0[nt], bh1[nt]);
                }
            }
        }
    }

    const bool doRope = n0 < ropeLim;
    float* Cp = C + (size_t)ks * NT * ldc;
    #pragma unroll
    for (int mh = 0; mh < MH; mh++) {
        #pragma unroll
        for (int nt = 0; nt < 4; nt++) {
            int r0 = wm*16*MH + mh*16 + g;
            int r1 = r0 + 8;
            int gc = n0 + wn*32 + nt*8 + 2*tg;
            float v0 = acc[mh][nt][0], v1 = acc[mh][nt][1];
            float v2 = acc[mh][nt][2], v3 = acc[mh][nt][3];
            float2 o0, o1;
            if (doRope) {
                int pd2 = (gc & (HD-1)) >> 1;
                const float* f0 = freqs + (r0 & (SEQ-1))*128 + pd2*2;
                const float* f1 = freqs + (r1 & (SEQ-1))*128 + pd2*2;
                float ca0 = f0[0], sa0 = f0[1];
                float ca1 = f1[0], sa1 = f1[1];
                o0.x = v0*ca0 - v1*sa0;  o0.y = v0*sa0 + v1*ca0;
                o1.x = v2*ca1 - v3*sa1;  o1.y = v2*sa1 + v3*ca1;
            } else {
                o0.x = v0; o0.y = v1; o1.x = v2; o1.y = v3;
            }
            *(float2*)&Cp[(size_t)r0 * ldc + gc] = o0;
            *(float2*)&Cp[(size_t)r1 * ldc + gc] = o1;
        }
    }
}

// ---------------------------------------------------------------------------
// Sum two split-K partials into out.
// ---------------------------------------------------------------------------
__global__ __launch_bounds__(256) void splitk_add(
    const float* __restrict__ pc, float* __restrict__ out)
{
    int i = blockIdx.x * 256 + threadIdx.x;
    float4 a = ((const float4*)pc)[i];
    float4 b = ((const float4*)pc)[(size_t)(NT*DIM/4) + i];
    float4 o = { a.x+b.x, a.y+b.y, a.z+b.z, a.w+b.w };
    ((float4*)out)[i] = o;
}

// ---------------------------------------------------------------------------
// Attention + fused cache write (exact R14 version; measured good).
// ---------------------------------------------------------------------------
#define AST 136
#define PST 40
#define CHK 32

#define O_QHI 0
#define O_QLO (O_QHI + 17408)
#define O_KHI (O_QLO + 17408)
#define O_KLO (O_KHI + 8704)
#define O_VHI (O_KLO + 8704)
#define O_VLO (O_VHI + 8704)
#define O_ST  (O_VLO + 8704)
#define O_PHI (O_ST  + 9216)
#define O_PLO (O_PHI + 5120)
#define O_MS  (O_PLO + 5120)
#define O_LS  (O_MS  + 256)
#define O_SCS (O_LS  + 256)
#define O_STG (O_SCS + 256)
#define ATTN_SMEM (O_STG + 16384)

__global__ __launch_bounds__(256, 2) void attn_mma(
    const float* __restrict__ qkv,
    const float* __restrict__ ckin, const float* __restrict__ cvin,
    float* __restrict__ outK, float* __restrict__ outV,
    const float* __restrict__ mask,
    float* __restrict__ po, float* __restrict__ pml)
{
    extern __shared__ char sm[];
    uint16_t* qhi = (uint16_t*)(sm + O_QHI);
    uint16_t* qlo = (uint16_t*)(sm + O_QLO);
    uint16_t* khi = (uint16_t*)(sm + O_KHI);
    uint16_t* klo = (uint16_t*)(sm + O_KLO);
    uint16_t* vhi = (uint16_t*)(sm + O_VHI);
    uint16_t* vlo = (uint16_t*)(sm + O_VLO);
    float*    s_t = (float*)(sm + O_ST);
    uint16_t* phi = (uint16_t*)(sm + O_PHI);
    uint16_t* plo = (uint16_t*)(sm + O_PLO);
    float*    m_s = (float*)(sm + O_MS);
    float*    l_s = (float*)(sm + O_LS);
    float*    sc_s= (float*)(sm + O_SCS);
    const float4* stg4 = (const float4*)(sm + O_STG);
    const uint32_t smb = smem_u32(sm);

    const int t    = threadIdx.x;
    const int wid  = t >> 5;
    const int lane = t & 31;
    const int g    = lane >> 2;
    const int tg   = lane & 3;
    const int wm   = wid >> 1;
    const int wn   = wid & 1;
    const int m0   = wm * 16;
    const int sp   = blockIdx.x;
    const int kvh  = blockIdx.y;
    const int b    = blockIdx.z;
    const int key0 = sp * KEYS_PER_SPLIT;

    auto ksrc = [&](int kpos) -> const float* {
        if (kpos < CL - SEQ)
            return ckin + ((size_t)(b*CL + kpos + SEQ)*NKV + kvh)*HD;
        return qkv + (size_t)(b*SEQ + (kpos - (CL - SEQ)))*NQKV + DIM + kvh*HD;
    };
    auto vsrc = [&](int kpos) -> const float* {
        if (kpos < CL - SEQ)
            return cvin + ((size_t)(b*CL + kpos + SEQ)*NKV + kvh)*HD;
        return qkv + (size_t)(b*SEQ + (kpos - (CL - SEQ)))*NQKV + DIM + NKV*HD + kvh*HD;
    };
    auto stageK = [&](int c0) {
        #pragma unroll
        for (int it = 0; it < 4; it++) {
            int idx = t + it*256;
            int key = idx >> 5, dq = idx & 31;
            cpasync16(smb + O_STG + (uint32_t)idx*16, ksrc(key0 + c0 + key) + dq*4);
        }
    };
    auto stageV = [&](int c0) {
        #pragma unroll
        for (int it = 0; it < 4; it++) {
            int idx = t + it*256;
            int key = idx >> 5, dq = idx & 31;
            cpasync16(smb + O_STG + (uint32_t)idx*16, vsrc(key0 + c0 + key) + dq*4);
        }
    };

    #pragma unroll
    for (int it = 0; it < 8; it++) {
        int idx = t + it*256;
        int q = idx >> 5, dq = idx & 31;
        const float* src = qkv + (size_t)(b*SEQ + (q & 15))*NQKV
                           + (kvh*4 + (q >> 4))*HD + dq*4;
        float4 v = *(const float4*)src;
        v.x *= RSQRT_HD; v.y *= RSQRT_HD; v.z *= RSQRT_HD; v.w *= RSQRT_HD;
        uint32_t h0, l0, h1, l1;
        split2(v.x, v.y, h0, l0);
        split2(v.z, v.w, h1, l1);
        int o = q*AST + dq*4;
        *(uint32_t*)&qhi[o] = h0;   *(uint32_t*)&qhi[o+2] = h1;
        *(uint32_t*)&qlo[o] = l0;   *(uint32_t*)&qlo[o+2] = l1;
    }
    if (t < 64) { m_s[t] = -1e30f; l_s[t] = 0.f; }

    stageK(0); CP_COMMIT();

    float accO[8][4] = {};

    for (int c0 = 0; c0 < KEYS_PER_SPLIT; c0 += CHK) {
        CP_WAIT0();
        #pragma unroll
        for (int it = 0; it < 4; it++) {
            int idx = t + it*256;
            int key = idx >> 5, dq = idx & 31;
            int kpos = key0 + c0 + key;
            float4 kv = stg4[idx];
            *(float4*)(outK + ((size_t)(b*CL + kpos)*NKV + kvh)*HD + dq*4) = kv;
            uint32_t h0, l0, h1, l1;
            int o = key*AST + dq*4;
            split2(kv.x, kv.y, h0, l0); split2(kv.z, kv.w, h1, l1);
            *(uint32_t*)&khi[o] = h0;  *(uint32_t*)&khi[o+2] = h1;
            *(uint32_t*)&klo[o] = l0;  *(uint32_t*)&klo[o+2] = l1;
        }
        __syncthreads();

        stageV(c0); CP_COMMIT();

        {
            float acc[2][4] = {};
            #pragma unroll
            for (int kk = 0; kk < 8; kk++) {
                const int kb = kk*16 + 2*tg;
                int ai = (m0 + g)*AST + kb;
                uint32_t ah0 = *(const uint32_t*)&qhi[ai];
                uint32_t ah1 = *(const uint32_t*)&qhi[ai + 8*AST];
                uint32_t ah2 = *(const uint32_t*)&qhi[ai + 8];
                uint32_t ah3 = *(const uint32_t*)&qhi[ai + 8*AST + 8];
                uint32_t al0 = *(const uint32_t*)&qlo[ai];
                uint32_t al1 = *(const uint32_t*)&qlo[ai + 8*AST];
                uint32_t al2 = *(const uint32_t*)&qlo[ai + 8];
                uint32_t al3 = *(const uint32_t*)&qlo[ai + 8*AST + 8];
                #pragma unroll
                for (int nf = 0; nf < 2; nf++) {
                    int bi = (wn*16 + nf*8 + g)*AST + kb;
                    uint32_t bh0 = *(const uint32_t*)&khi[bi];
                    uint32_t bh1 = *(const uint32_t*)&khi[bi + 8];
                    uint32_t bl0 = *(const uint32_t*)&klo[bi];
                    uint32_t bl1 = *(const uint32_t*)&klo[bi + 8];
                    MMA_BF16(acc[nf], ah0, ah1, ah2, ah3, bh0, bh1);
                    MMA_BF16(acc[nf], ah0, ah1, ah2, ah3, bl0, bl1);
                    MMA_BF16(acc[nf], al0, al1, al2, al3, bh0, bh1);
                }
            }
            #pragma unroll
            for (int nf = 0; nf < 2; nf++) {
                int col = wn*16 + nf*8 + 2*tg;
                float2 lo2 = { acc[nf][0], acc[nf][1] };
                float2 hi2 = { acc[nf][2], acc[nf][3] };
                *(float2*)&s_t[(m0+g)*36 + col]   = lo2;
                *(float2*)&s_t[(m0+g+8)*36 + col] = hi2;
            }
        }
        __syncthreads();

        CP_WAIT0();
        #pragma unroll
        for (int it = 0; it < 4; it++) {
            int idx = t + it*256;
            int key = idx >> 5, dq = idx & 31;
            int kpos = key0 + c0 + key;
            float4 vv = stg4[idx];
            *(float4*)(outV + ((size_t)(b*CL + kpos)*NKV + kvh)*HD + dq*4) = vv;
            uint32_t h0, l0, h1, l1;
            int o = key*AST + dq*4;
            split2(vv.x, vv.y, h0, l0); split2(vv.z, vv.w, h1, l1);
            *(uint32_t*)&vhi[o] = h0;  *(uint32_t*)&vhi[o+2] = h1;
            *(uint32_t*)&vlo[o] = l0;  *(uint32_t*)&vlo[o+2] = l1;
        }

        #pragma unroll
        for (int rr = 0; rr < 8; rr++) {
            int q = wid*8 + rr;
            int s = q & 15;
            float v0 = s_t[q*36 + lane] + mask[(size_t)s*CL + key0 + c0 + lane];
            float mx = v0;
            #pragma unroll
            for (int o = 16; o; o >>= 1) mx = fmaxf(mx, __shfl_xor_sync(0xffffffffu, mx, o));
            float mnew = fmaxf(m_s[q], mx);
            float p0 = __expf(v0 - mnew);
            uint32_t u0 = __float_as_uint(p0);
            float h0 = __uint_as_float(u0 & 0xFFFF0000u);
            phi[q*PST + lane] = (uint16_t)(u0 >> 16);
            plo[q*PST + lane] = (uint16_t)(__float_as_uint(p0 - h0) >> 16);
            float sum = p0;
            #pragma unroll
            for (int o = 16; o; o >>= 1) sum += __shfl_xor_sync(0xffffffffu, sum, o);
            if (lane == 0) {
                float sc = __expf(m_s[q] - mnew);
                sc_s[q] = sc;
                l_s[q]  = l_s[q] * sc + sum;
                m_s[q]  = mnew;
            }
        }
        __syncthreads();

        if (c0 + CHK < KEYS_PER_SPLIT) { stageK(c0 + CHK); CP_COMMIT(); }

        {
            float sc0 = sc_s[m0 + g];
            float sc1 = sc_s[m0 + g + 8];
            #pragma unroll
            for (int nf = 0; nf < 8; nf++) {
                accO[nf][0] *= sc0; accO[nf][1] *= sc0;
                accO[nf][2] *= sc1; accO[nf][3] *= sc1;
            }
            #pragma unroll
            for (int kk = 0; kk < 2; kk++) {
                const int kb = kk*16 + 2*tg;
                int ai = (m0 + g)*PST + kb;
                uint32_t ah0 = *(const uint32_t*)&phi[ai];
                uint32_t ah1 = *(const uint32_t*)&phi[ai + 8*PST];
                uint32_t ah2 = *(const uint32_t*)&phi[ai + 8];
                uint32_t ah3 = *(const uint32_t*)&phi[ai + 8*PST + 8];
                uint32_t al0 = *(const uint32_t*)&plo[ai];
                uint32_t al1 = *(const uint32_t*)&plo[ai + 8*PST];
                uint32_t al2 = *(const uint32_t*)&plo[ai + 8];
                uint32_t al3 = *(const uint32_t*)&plo[ai + 8*PST + 8];
                #pragma unroll
                for (int dd = 0; dd < 4; dd++) {
                    int d0 = wn*64 + dd*16;
                    uint32_t rowa = (uint32_t)((kk*16 + (lane & 15))*AST
                                    + d0 + (lane >> 4)*8) * 2u;
                    uint32_t bh0, bh1, bh2, bh3, bl0, bl1, bl2, bl3;
                    ldmx4t(bh0, bh1, bh2, bh3, smb + O_VHI + rowa);
                    ldmx4t(bl0, bl1, bl2, bl3, smb + O_VLO + rowa);
                    MMA_BF16(accO[dd*2],   ah0, ah1, ah2, ah3, bh0, bh1);
                    MMA_BF16(accO[dd*2],   al0, al1, al2, al3, bh0, bh1);
                    MMA_BF16(accO[dd*2],   ah0, ah1, ah2, ah3, bl0, bl1);
                    MMA_BF16(accO[dd*2+1], ah0, ah1, ah2, ah3, bh2, bh3);
                    MMA_BF16(accO[dd*2+1], al0, al1, al2, al3, bh2, bh3);
                    MMA_BF16(accO[dd*2+1], ah0, ah1, ah2, ah3, bl2, bl3);
                }
            }
        }
    }

    size_t base = ((size_t)(b*NKV + kvh)*NSPLIT + sp)*64;
    #pragma unroll
    for (int nf = 0; nf < 8; nf++) {
        int col = wn*64 + nf*8 + 2*tg;
        float2 lo2 = { accO[nf][0], accO[nf][1] };
        float2 hi2 = { accO[nf][2], accO[nf][3] };
        *(float2*)&po[(base + m0 + g)*128 + col]     = lo2;
        *(float2*)&po[(base + m0 + g + 8)*128 + col] = hi2;
    }
    if (t < 64) {
        pml[(base + t)*2 + 0] = m_s[t];
        pml[(base + t)*2 + 1] = l_s[t];
    }
}

// ---------------------------------------------------------------------------
// Combine split-KV partials -> pre-split bf16 attn output (R12 version,
// measured 8.7us).  grid (64, 4); thread handles adjacent d pairs.
// ---------------------------------------------------------------------------
__global__ __launch_bounds__(256) void attn_combine(
    const float* __restrict__ po, const float* __restrict__ pml,
    uint16_t* __restrict__ ahi, uint16_t* __restrict__ alo)
{
    __shared__ float wsm[NSPLIT][64];
    __shared__ float linv[64];
    const int t  = threadIdx.x;
    const int bk = blockIdx.x;
    if (t < 64) {
        float mv[NSPLIT];
        float M = -1e30f;
        #pragma unroll
        for (int i = 0; i < NSPLIT; i++) {
            mv[i] = pml[((size_t)(bk*NSPLIT + i)*64 + t)*2 + 0];
            M = fmaxf(M, mv[i]);
        }
        float L = 0.f;
        #pragma unroll
        for (int i = 0; i < NSPLIT; i++) {
            float w = __expf(mv[i] - M);
            wsm[i][t] = w;
            L += w * pml[((size_t)(bk*NSPLIT + i)*64 + t)*2 + 1];
        }
        linv[t] = 1.f / L;
    }
    __syncthreads();
    const int dp = blockIdx.y*16 + (t & 15);   // d-pair 0..63
    const int d0 = dp*2;
    const int qr = t >> 4;                     // 0..15
    const int b = bk >> 3, kvh = bk & 7;
    for (int q = qr; q < 64; q += 16) {
        float o0 = 0.f, o1 = 0.f;
        #pragma unroll
        for (int i = 0; i < NSPLIT; i++) {
            float2 p = *(const float2*)&po[((size_t)(bk*NSPLIT + i)*64 + q)*128 + d0];
            float w = wsm[i][q];
            o0 += p.x * w;
            o1 += p.y * w;
        }
        float li = linv[q];
        o0 *= li; o1 *= li;
        uint32_t hi, lo;
        split2(o0, o1, hi, lo);
        int s = q & 15, hh = q >> 4;
        size_t ofs = (size_t)(b*SEQ + s)*DIM + (kvh*4 + hh)*HD + d0;
        *(uint32_t*)&ahi[ofs] = hi;
        *(uint32_t*)&alo[ofs] = lo;
    }
}

// ---------------------------------------------------------------------------
extern "C" void kernel_launch(void* const* d_in, const int* in_sizes, int n_in,
                              void* d_out, int out_size)
{
    const float* x     = (const float*)d_in[0];
    const float* mask  = (const float*)d_in[1];
    const float* freqs = (const float*)d_in[2];
    const float* ck    = (const float*)d_in[3];
    const float* cv    = (const float*)d_in[4];
    const float* wq    = (const float*)d_in[5];
    const float* wk    = (const float*)d_in[6];
    const float* wv    = (const float*)d_in[7];
    const float* wo    = (const float*)d_in[8];
    float* out = (float*)d_out;

    float *qkv, *po, *pml, *pc;
    uint16_t *xhi, *xlo, *ahi, *alo;
    cudaGetSymbolAddress((void**)&qkv, g_qkv);
    cudaGetSymbolAddress((void**)&po,  g_po);
    cudaGetSymbolAddress((void**)&pml, g_pml);
    cudaGetSymbolAddress((void**)&pc,  g_pc);
    cudaGetSymbolAddress((void**)&xhi, g_xhi);
    cudaGetSymbolAddress((void**)&xlo, g_xlo);
    cudaGetSymbolAddress((void**)&ahi, g_ahi);
    cudaGetSymbolAddress((void**)&alo, g_alo);

    const int GEMM_SMEM64 = (2*128*ASTR + 2*64*ASTR) * 2;   // 55296
    const int GEMM_SMEM32 = (2*128*ASTR + 2*32*ASTR) * 2;   // 46080
    static int smem_set = 0;
    if (!smem_set) {
        cudaFuncSetAttribute(gemm_mma<64>, cudaFuncAttributeMaxDynamicSharedMemorySize, GEMM_SMEM64);
        cudaFuncSetAttribute(gemm_mma<32>, cudaFuncAttributeMaxDynamicSharedMemorySize, GEMM_SMEM32);
        cudaFuncSetAttribute(attn_mma, cudaFuncAttributeMaxDynamicSharedMemorySize, ATTN_SMEM);
        smem_set = 1;
    }

    // Pre-split x, then fused QKV projection + RoPE epilogue (BN=64)
    convert_x<<<512, 256>>>(x, xhi, xlo);
    gemm_mma<64><<<dim3(NQKV/64, 1), 256, GEMM_SMEM64>>>(
        xhi, xlo, wq, wk, wv, qkv, NQKV, freqs, ROPE_LIM);

    // Attention with fused cache writes + async K/V staging, then combine
    attn_mma<<<dim3(NSPLIT, NKV, BSZ), 256, ATTN_SMEM>>>(
        qkv, ck, cv, out + CK_OFF, out + CV_OFF, mask, po, pml);
    attn_combine<<<dim3(BSZ*NKV, 4), 256>>>(po, pml, ahi, alo);

    // Output projection: BN=32, split-K=2 (256 blocks) + partial sum
    gemm_mma<32><<<dim3(DIM/32, 2), 256, GEMM_SMEM32>>>(
        ahi, alo, wo, nullptr, nullptr, pc, DIM, nullptr, 0);
    splitk_add<<<512, 256>>>(pc, out);
}

// round 16
// speedup vs baseline: 1.0768x; 1.0768x over previous
#include <cuda_runtime.h>
#include <cstdint>

#define BSZ 8
#define SEQ 16
#define DIM 4096
#define NH 32
#define NKV 8
#define HD 128
#define CL 4096
#define NT (BSZ*SEQ)                 // 128 tokens
#define NQKV (DIM + 2*NKV*HD)        // 6144
#define ROPE_LIM (DIM + NKV*HD)      // 5120
#define CACHE_ELEMS (BSZ*CL*NKV*HD)
#define CK_OFF ((size_t)NT*DIM)
#define CV_OFF (CK_OFF + CACHE_ELEMS)
#define RSQRT_HD 0.08838834764831845f
#define NSPLIT 8
#define KEYS_PER_SPLIT (CL/NSPLIT)   // 512

typedef unsigned long long ull;

__device__ float g_qkv[(size_t)NT*NQKV];
__device__ float g_attn[(size_t)NT*DIM];
__device__ float g_po[(size_t)BSZ*NKV*NSPLIT*64*128];
__device__ float g_pml[(size_t)BSZ*NKV*NSPLIT*64*2];
__device__ float g_pc[(size_t)2*NT*DIM];          // WO split-K partials
__device__ float g_pq[(size_t)2*NT*NQKV];         // QKV split-K partials

// ---- bf16 mma.sync (baseline sm_80+ ISA) ----------------------------------
#define MMA_BF16(d, a0,a1,a2,a3, b0,b1) \
    asm volatile( \
        "mma.sync.aligned.m16n8k16.row.col.f32.bf16.bf16.f32 " \
        "{%0,%1,%2,%3}, {%4,%5,%6,%7}, {%8,%9}, {%0,%1,%2,%3};" \
        : "+f"(d[0]), "+f"(d[1]), "+f"(d[2]), "+f"(d[3]) \
        : "r"(a0), "r"(a1), "r"(a2), "r"(a3), "r"(b0), "r"(b1))

__device__ __forceinline__ void ldmx4t(uint32_t& r0, uint32_t& r1,
                                       uint32_t& r2, uint32_t& r3, uint32_t addr) {
    asm volatile("ldmatrix.sync.aligned.m8n8.x4.trans.shared.b16 {%0,%1,%2,%3}, [%4];"
        : "=r"(r0), "=r"(r1), "=r"(r2), "=r"(r3) : "r"(addr));
}
__device__ __forceinline__ uint32_t smem_u32(const void* p) {
    uint32_t a;
    asm("{ .reg .u64 t; cvta.to.shared.u64 t, %1; cvt.u32.u64 %0, t; }"
        : "=r"(a) : "l"(p));
    return a;
}
__device__ __forceinline__ void cpasync16(uint32_t dst, const void* src) {
    asm volatile("cp.async.cg.shared.global [%0], [%1], 16;"
                 :: "r"(dst), "l"(src) : "memory");
}
#define CP_COMMIT() asm volatile("cp.async.commit_group;" ::: "memory")
#define CP_WAIT0()  asm volatile("cp.async.wait_group 0;" ::: "memory")

// split one float pair -> (hi bf16x2, lo bf16x2); first element in low half
__device__ __forceinline__ void split2(float x, float y, uint32_t& hi, uint32_t& lo) {
    uint32_t ux = __float_as_uint(x), uy = __float_as_uint(y);
    float hx = __uint_as_float(ux & 0xFFFF0000u);
    float hy = __uint_as_float(uy & 0xFFFF0000u);
    hi = __byte_perm(ux, uy, 0x7632);
    lo = __byte_perm(__float_as_uint(x - hx), __float_as_uint(y - hy), 0x7632);
}

// ---------------------------------------------------------------------------
// Tensor-core GEMM (split-bf16 mma.sync, fp32 A converted in-kernel),
// templated on BN. Split-K via gridDim.y (partials at C + ks*NT*ldc).
// No rope here — rope applied in the partial-sum pass.
// ---------------------------------------------------------------------------
#define BKS 64
#define ASTR 72
#define U16_AHI 0
#define U16_ALO (128*ASTR)
#define U16_WHI (2*128*ASTR)

template<int BN>
__global__ __launch_bounds__(256) void gemm_mma(
    const float* __restrict__ A,
    const float* __restrict__ W0, const float* __restrict__ W1,
    const float* __restrict__ W2,
    float* __restrict__ C, int ldc)
{
    extern __shared__ char smraw[];
    uint16_t* sm16 = (uint16_t*)smraw;
    constexpr int MH = BN / 32;
    constexpr int WLO = 2*128*ASTR + BN*ASTR;

    const int t    = threadIdx.x;
    const int wid  = t >> 5;
    const int lane = t & 31;
    const int g    = lane >> 2;
    const int tg   = lane & 3;
    const int wm   = (BN == 64) ? (wid >> 1) : wid;
    const int wn   = (BN == 64) ? (wid & 1) : 0;
    const int n0   = blockIdx.x * BN;
    const int ks   = blockIdx.y;
    const int kbase = ks * (DIM / gridDim.y);
    const int nstg  = DIM / gridDim.y / BKS;

    const float* W = W0; int nr = n0;
    if (W1 != nullptr && n0 >= DIM) {
        if (n0 < DIM + NKV*HD) { W = W1; nr = n0 - DIM; }
        else                   { W = W2; nr = n0 - DIM - NKV*HD; }
    }

    float acc[MH][4][4] = {};
    float4 pa[8], pw[BN/16];

    #pragma unroll
    for (int it = 0; it < 8; it++) {
        int v = t + it*256, row = v >> 4, gq = v & 15;
        pa[it] = *(const float4*)(A + (size_t)row * DIM + kbase + gq*4);
    }
    #pragma unroll
    for (int it = 0; it < BN/16; it++) {
        int v = t + it*256, row = v >> 4, gq = v & 15;
        pw[it] = *(const float4*)(W + (size_t)(nr + row) * DIM + kbase + gq*4);
    }

    for (int st = 0; st < nstg; st++) {
        __syncthreads();
        #pragma unroll
        for (int it = 0; it < 8; it++) {
            int v = t + it*256, row = v >> 4, gq = v & 15;
            int idx = row*ASTR + gq*4;
            uint32_t h0, l0, h1, l1;
            split2(pa[it].x, pa[it].y, h0, l0);
            split2(pa[it].z, pa[it].w, h1, l1);
            *(uint32_t*)&sm16[U16_AHI + idx]     = h0;
            *(uint32_t*)&sm16[U16_AHI + idx + 2] = h1;
            *(uint32_t*)&sm16[U16_ALO + idx]     = l0;
            *(uint32_t*)&sm16[U16_ALO + idx + 2] = l1;
        }
        #pragma unroll
        for (int it = 0; it < BN/16; it++) {
            int v = t + it*256, row = v >> 4, gq = v & 15;
            int idx = row*ASTR + gq*4;
            uint32_t h0, l0, h1, l1;
            split2(pw[it].x, pw[it].y, h0, l0);
            split2(pw[it].z, pw[it].w, h1, l1);
            *(uint32_t*)&sm16[U16_WHI + idx]     = h0;
            *(uint32_t*)&sm16[U16_WHI + idx + 2] = h1;
            *(uint32_t*)&sm16[WLO + idx]     = l0;
            *(uint32_t*)&sm16[WLO + idx + 2] = l1;
        }
        __syncthreads();

        if (st + 1 < nstg) {
            const int k0 = kbase + (st + 1) * BKS;
            #pragma unroll
            for (int it = 0; it < 8; it++) {
                int v = t + it*256, row = v >> 4, gq = v & 15;
                pa[it] = *(const float4*)(A + (size_t)row * DIM + k0 + gq*4);
            }
            #pragma unroll
            for (int it = 0; it < BN/16; it++) {
                int v = t + it*256, row = v >> 4, gq = v & 15;
                pw[it] = *(const float4*)(W + (size_t)(nr + row) * DIM + k0 + gq*4);
            }
        }

        #pragma unroll
        for (int kk = 0; kk < 4; kk++) {
            const int kb = kk*16 + 2*tg;
            uint32_t bh0[4], bh1[4], bl0[4], bl1[4];
            #pragma unroll
            for (int nt = 0; nt < 4; nt++) {
                int bi = (wn*32 + nt*8 + g)*ASTR + kb;
                bh0[nt] = *(const uint32_t*)&sm16[U16_WHI + bi];
                bh1[nt] = *(const uint32_t*)&sm16[U16_WHI + bi + 8];
                bl0[nt] = *(const uint32_t*)&sm16[WLO + bi];
                bl1[nt] = *(const uint32_t*)&sm16[WLO + bi + 8];
            }
            #pragma unroll
            for (int mh = 0; mh < MH; mh++) {
                int ai = (wm*16*MH + mh*16 + g)*ASTR + kb;
                uint32_t ah0 = *(const uint32_t*)&sm16[U16_AHI + ai];
                uint32_t ah1 = *(const uint32_t*)&sm16[U16_AHI + ai + 8*ASTR];
                uint32_t ah2 = *(const uint32_t*)&sm16[U16_AHI + ai + 8];
                uint32_t ah3 = *(const uint32_t*)&sm16[U16_AHI + ai + 8*ASTR + 8];
                uint32_t al0 = *(const uint32_t*)&sm16[U16_ALO + ai];
                uint32_t al1 = *(const uint32_t*)&sm16[U16_ALO + ai + 8*ASTR];
                uint32_t al2 = *(const uint32_t*)&sm16[U16_ALO + ai + 8];
                uint32_t al3 = *(const uint32_t*)&sm16[U16_ALO + ai + 8*ASTR + 8];
                #pragma unroll
                for (int nt = 0; nt < 4; nt++) {
                    MMA_BF16(acc[mh][nt], ah0, ah1, ah2, ah3, bh0[nt], bh1[nt]);
                    MMA_BF16(acc[mh][nt], ah0, ah1, ah2, ah3, bl0[nt], bl1[nt]);
                    MMA_BF16(acc[mh][nt], al0, al1, al2, al3, bh0[nt], bh1[nt]);
                }
            }
        }
    }

    float* Cp = C + (size_t)ks * NT * ldc;
    #pragma unroll
    for (int mh = 0; mh < MH; mh++) {
        #pragma unroll
        for (int nt = 0; nt < 4; nt++) {
            int r0 = wm*16*MH + mh*16 + g;
            int r1 = r0 + 8;
            int gc = n0 + wn*32 + nt*8 + 2*tg;
            float2 o0 = { acc[mh][nt][0], acc[mh][nt][1] };
            float2 o1 = { acc[mh][nt][2], acc[mh][nt][3] };
            *(float2*)&Cp[(size_t)r0 * ldc + gc] = o0;
            *(float2*)&Cp[(size_t)r1 * ldc + gc] = o1;
        }
    }
}

// ---------------------------------------------------------------------------
// Sum two QKV split-K partials + RoPE -> g_qkv.  196608 float4s, grid 768.
// ---------------------------------------------------------------------------
__global__ __launch_bounds__(256) void qkv_add_rope(
    const float* __restrict__ pq, float* __restrict__ qkv,
    const float* __restrict__ freqs)
{
    int i = blockIdx.x * 256 + threadIdx.x;       // float4 index over NT*NQKV/4
    float4 a = ((const float4*)pq)[i];
    float4 b = ((const float4*)pq)[(size_t)(NT*NQKV/4) + i];
    float v0 = a.x + b.x, v1 = a.y + b.y, v2 = a.z + b.z, v3 = a.w + b.w;
    int col = (i * 4) % NQKV;
    int row = (i * 4) / NQKV;
    float4 o;
    if (col < ROPE_LIM) {
        int s = row & (SEQ - 1);
        int pd2 = (col & (HD - 1)) >> 1;
        const float* f = freqs + s*128 + pd2*2;   // [cos0,sin0,cos1,sin1]
        float ca = f[0], sa = f[1], cb = f[2], sb = f[3];
        o.x = v0*ca - v1*sa;  o.y = v0*sa + v1*ca;
        o.z = v2*cb - v3*sb;  o.w = v2*sb + v3*cb;
    } else {
        o.x = v0; o.y = v1; o.z = v2; o.w = v3;
    }
    ((float4*)qkv)[i] = o;
}

// ---------------------------------------------------------------------------
// Sum two WO split-K partials into out.
// ---------------------------------------------------------------------------
__global__ __launch_bounds__(256) void splitk_add(
    const float* __restrict__ pc, float* __restrict__ out)
{
    int i = blockIdx.x * 256 + threadIdx.x;
    float4 a = ((const float4*)pc)[i];
    float4 b = ((const float4*)pc)[(size_t)(NT*DIM/4) + i];
    float4 o = { a.x+b.x, a.y+b.y, a.z+b.z, a.w+b.w };
    ((float4*)out)[i] = o;
}

// ---------------------------------------------------------------------------
// Attention + fused cache write (exact R14 version; measured good).
// ---------------------------------------------------------------------------
#define AST 136
#define PST 40
#define CHK 32

#define O_QHI 0
#define O_QLO (O_QHI + 17408)
#define O_KHI (O_QLO + 17408)
#define O_KLO (O_KHI + 8704)
#define O_VHI (O_KLO + 8704)
#define O_VLO (O_VHI + 8704)
#define O_ST  (O_VLO + 8704)
#define O_PHI (O_ST  + 9216)
#define O_PLO (O_PHI + 5120)
#define O_MS  (O_PLO + 5120)
#define O_LS  (O_MS  + 256)
#define O_SCS (O_LS  + 256)
#define O_STG (O_SCS + 256)
#define ATTN_SMEM (O_STG + 16384)

__global__ __launch_bounds__(256, 2) void attn_mma(
    const float* __restrict__ qkv,
    const float* __restrict__ ckin, const float* __restrict__ cvin,
    float* __restrict__ outK, float* __restrict__ outV,
    const float* __restrict__ mask,
    float* __restrict__ po, float* __restrict__ pml)
{
    extern __shared__ char sm[];
    uint16_t* qhi = (uint16_t*)(sm + O_QHI);
    uint16_t* qlo = (uint16_t*)(sm + O_QLO);
    uint16_t* khi = (uint16_t*)(sm + O_KHI);
    uint16_t* klo = (uint16_t*)(sm + O_KLO);
    uint16_t* vhi = (uint16_t*)(sm + O_VHI);
    uint16_t* vlo = (uint16_t*)(sm + O_VLO);
    float*    s_t = (float*)(sm + O_ST);
    uint16_t* phi = (uint16_t*)(sm + O_PHI);
    uint16_t* plo = (uint16_t*)(sm + O_PLO);
    float*    m_s = (float*)(sm + O_MS);
    float*    l_s = (float*)(sm + O_LS);
    float*    sc_s= (float*)(sm + O_SCS);
    const float4* stg4 = (const float4*)(sm + O_STG);
    const uint32_t smb = smem_u32(sm);

    const int t    = threadIdx.x;
    const int wid  = t >> 5;
    const int lane = t & 31;
    const int g    = lane >> 2;
    const int tg   = lane & 3;
    const int wm   = wid >> 1;
    const int wn   = wid & 1;
    const int m0   = wm * 16;
    const int sp   = blockIdx.x;
    const int kvh  = blockIdx.y;
    const int b    = blockIdx.z;
    const int key0 = sp * KEYS_PER_SPLIT;

    auto ksrc = [&](int kpos) -> const float* {
        if (kpos < CL - SEQ)
            return ckin + ((size_t)(b*CL + kpos + SEQ)*NKV + kvh)*HD;
        return qkv + (size_t)(b*SEQ + (kpos - (CL - SEQ)))*NQKV + DIM + kvh*HD;
    };
    auto vsrc = [&](int kpos) -> const float* {
        if (kpos < CL - SEQ)
            return cvin + ((size_t)(b*CL + kpos + SEQ)*NKV + kvh)*HD;
        return qkv + (size_t)(b*SEQ + (kpos - (CL - SEQ)))*NQKV + DIM + NKV*HD + kvh*HD;
    };
    auto stageK = [&](int c0) {
        #pragma unroll
        for (int it = 0; it < 4; it++) {
            int idx = t + it*256;
            int key = idx >> 5, dq = idx & 31;
            cpasync16(smb + O_STG + (uint32_t)idx*16, ksrc(key0 + c0 + key) + dq*4);
        }
    };
    auto stageV = [&](int c0) {
        #pragma unroll
        for (int it = 0; it < 4; it++) {
            int idx = t + it*256;
            int key = idx >> 5, dq = idx & 31;
            cpasync16(smb + O_STG + (uint32_t)idx*16, vsrc(key0 + c0 + key) + dq*4);
        }
    };

    #pragma unroll
    for (int it = 0; it < 8; it++) {
        int idx = t + it*256;
        int q = idx >> 5, dq = idx & 31;
        const float* src = qkv + (size_t)(b*SEQ + (q & 15))*NQKV
                           + (kvh*4 + (q >> 4))*HD + dq*4;
        float4 v = *(const float4*)src;
        v.x *= RSQRT_HD; v.y *= RSQRT_HD; v.z *= RSQRT_HD; v.w *= RSQRT_HD;
        uint32_t h0, l0, h1, l1;
        split2(v.x, v.y, h0, l0);
        split2(v.z, v.w, h1, l1);
        int o = q*AST + dq*4;
        *(uint32_t*)&qhi[o] = h0;   *(uint32_t*)&qhi[o+2] = h1;
        *(uint32_t*)&qlo[o] = l0;   *(uint32_t*)&qlo[o+2] = l1;
    }
    if (t < 64) { m_s[t] = -1e30f; l_s[t] = 0.f; }

    stageK(0); CP_COMMIT();

    float accO[8][4] = {};

    for (int c0 = 0; c0 < KEYS_PER_SPLIT; c0 += CHK) {
        CP_WAIT0();
        #pragma unroll
        for (int it = 0; it < 4; it++) {
            int idx = t + it*256;
            int key = idx >> 5, dq = idx & 31;
            int kpos = key0 + c0 + key;
            float4 kv = stg4[idx];
            *(float4*)(outK + ((size_t)(b*CL + kpos)*NKV + kvh)*HD + dq*4) = kv;
            uint32_t h0, l0, h1, l1;
            int o = key*AST + dq*4;
            split2(kv.x, kv.y, h0, l0); split2(kv.z, kv.w, h1, l1);
            *(uint32_t*)&khi[o] = h0;  *(uint32_t*)&khi[o+2] = h1;
            *(uint32_t*)&klo[o] = l0;  *(uint32_t*)&klo[o+2] = l1;
        }
        __syncthreads();

        stageV(c0); CP_COMMIT();

        {
            float acc[2][4] = {};
            #pragma unroll
            for (int kk = 0; kk < 8; kk++) {
                const int kb = kk*16 + 2*tg;
                int ai = (m0 + g)*AST + kb;
                uint32_t ah0 = *(const uint32_t*)&qhi[ai];
                uint32_t ah1 = *(const uint32_t*)&qhi[ai + 8*AST];
                uint32_t ah2 = *(const uint32_t*)&qhi[ai + 8];
                uint32_t ah3 = *(const uint32_t*)&qhi[ai + 8*AST + 8];
                uint32_t al0 = *(const uint32_t*)&qlo[ai];
                uint32_t al1 = *(const uint32_t*)&qlo[ai + 8*AST];
                uint32_t al2 = *(const uint32_t*)&qlo[ai + 8];
                uint32_t al3 = *(const uint32_t*)&qlo[ai + 8*AST + 8];
                #pragma unroll
                for (int nf = 0; nf < 2; nf++) {
                    int bi = (wn*16 + nf*8 + g)*AST + kb;
                    uint32_t bh0 = *(const uint32_t*)&khi[bi];
                    uint32_t bh1 = *(const uint32_t*)&khi[bi + 8];
                    uint32_t bl0 = *(const uint32_t*)&klo[bi];
                    uint32_t bl1 = *(const uint32_t*)&klo[bi + 8];
                    MMA_BF16(acc[nf], ah0, ah1, ah2, ah3, bh0, bh1);
                    MMA_BF16(acc[nf], ah0, ah1, ah2, ah3, bl0, bl1);
                    MMA_BF16(acc[nf], al0, al1, al2, al3, bh0, bh1);
                }
            }
            #pragma unroll
            for (int nf = 0; nf < 2; nf++) {
                int col = wn*16 + nf*8 + 2*tg;
                float2 lo2 = { acc[nf][0], acc[nf][1] };
                float2 hi2 = { acc[nf][2], acc[nf][3] };
                *(float2*)&s_t[(m0+g)*36 + col]   = lo2;
                *(float2*)&s_t[(m0+g+8)*36 + col] = hi2;
            }
        }
        __syncthreads();

        CP_WAIT0();
        #pragma unroll
        for (int it = 0; it < 4; it++) {
            int idx = t + it*256;
            int key = idx >> 5, dq = idx & 31;
            int kpos = key0 + c0 + key;
            float4 vv = stg4[idx];
            *(float4*)(outV + ((size_t)(b*CL + kpos)*NKV + kvh)*HD + dq*4) = vv;
            uint32_t h0, l0, h1, l1;
            int o = key*AST + dq*4;
            split2(vv.x, vv.y, h0, l0); split2(vv.z, vv.w, h1, l1);
            *(uint32_t*)&vhi[o] = h0;  *(uint32_t*)&vhi[o+2] = h1;
            *(uint32_t*)&vlo[o] = l0;  *(uint32_t*)&vlo[o+2] = l1;
        }

        #pragma unroll
        for (int rr = 0; rr < 8; rr++) {
            int q = wid*8 + rr;
            int s = q & 15;
            float v0 = s_t[q*36 + lane] + mask[(size_t)s*CL + key0 + c0 + lane];
            float mx = v0;
            #pragma unroll
            for (int o = 16; o; o >>= 1) mx = fmaxf(mx, __shfl_xor_sync(0xffffffffu, mx, o));
            float mnew = fmaxf(m_s[q], mx);
            float p0 = __expf(v0 - mnew);
            uint32_t u0 = __float_as_uint(p0);
            float h0 = __uint_as_float(u0 & 0xFFFF0000u);
            phi[q*PST + lane] = (uint16_t)(u0 >> 16);
            plo[q*PST + lane] = (uint16_t)(__float_as_uint(p0 - h0) >> 16);
            float sum = p0;
            #pragma unroll
            for (int o = 16; o; o >>= 1) sum += __shfl_xor_sync(0xffffffffu, sum, o);
            if (lane == 0) {
                float sc = __expf(m_s[q] - mnew);
                sc_s[q] = sc;
                l_s[q]  = l_s[q] * sc + sum;
                m_s[q]  = mnew;
            }
        }
        __syncthreads();

        if (c0 + CHK < KEYS_PER_SPLIT) { stageK(c0 + CHK); CP_COMMIT(); }

        {
            float sc0 = sc_s[m0 + g];
            float sc1 = sc_s[m0 + g + 8];
            #pragma unroll
            for (int nf = 0; nf < 8; nf++) {
                accO[nf][0] *= sc0; accO[nf][1] *= sc0;
                accO[nf][2] *= sc1; accO[nf][3] *= sc1;
            }
            #pragma unroll
            for (int kk = 0; kk < 2; kk++) {
                const int kb = kk*16 + 2*tg;
                int ai = (m0 + g)*PST + kb;
                uint32_t ah0 = *(const uint32_t*)&phi[ai];
                uint32_t ah1 = *(const uint32_t*)&phi[ai + 8*PST];
                uint32_t ah2 = *(const uint32_t*)&phi[ai + 8];
                uint32_t ah3 = *(const uint32_t*)&phi[ai + 8*PST + 8];
                uint32_t al0 = *(const uint32_t*)&plo[ai];
                uint32_t al1 = *(const uint32_t*)&plo[ai + 8*PST];
                uint32_t al2 = *(const uint32_t*)&plo[ai + 8];
                uint32_t al3 = *(const uint32_t*)&plo[ai + 8*PST + 8];
                #pragma unroll
                for (int dd = 0; dd < 4; dd++) {
                    int d0 = wn*64 + dd*16;
                    uint32_t rowa = (uint32_t)((kk*16 + (lane & 15))*AST
                                    + d0 + (lane >> 4)*8) * 2u;
                    uint32_t bh0, bh1, bh2, bh3, bl0, bl1, bl2, bl3;
                    ldmx4t(bh0, bh1, bh2, bh3, smb + O_VHI + rowa);
                    ldmx4t(bl0, bl1, bl2, bl3, smb + O_VLO + rowa);
                    MMA_BF16(accO[dd*2],   ah0, ah1, ah2, ah3, bh0, bh1);
                    MMA_BF16(accO[dd*2],   al0, al1, al2, al3, bh0, bh1);
                    MMA_BF16(accO[dd*2],   ah0, ah1, ah2, ah3, bl0, bl1);
                    MMA_BF16(accO[dd*2+1], ah0, ah1, ah2, ah3, bh2, bh3);
                    MMA_BF16(accO[dd*2+1], al0, al1, al2, al3, bh2, bh3);
                    MMA_BF16(accO[dd*2+1], ah0, ah1, ah2, ah3, bl2, bl3);
                }
            }
        }
    }

    size_t base = ((size_t)(b*NKV + kvh)*NSPLIT + sp)*64;
    #pragma unroll
    for (int nf = 0; nf < 8; nf++) {
        int col = wn*64 + nf*8 + 2*tg;
        float2 lo2 = { accO[nf][0], accO[nf][1] };
        float2 hi2 = { accO[nf][2], accO[nf][3] };
        *(float2*)&po[(base + m0 + g)*128 + col]     = lo2;
        *(float2*)&po[(base + m0 + g + 8)*128 + col] = hi2;
    }
    if (t < 64) {
        pml[(base + t)*2 + 0] = m_s[t];
        pml[(base + t)*2 + 1] = l_s[t];
    }
}

// ---------------------------------------------------------------------------
// Combine split-KV partials -> attn output.  grid (64, 4): bk x d-slice.
// ---------------------------------------------------------------------------
__global__ __launch_bounds__(256) void attn_combine(
    const float* __restrict__ po, const float* __restrict__ pml,
    float* __restrict__ attn_out)
{
    __shared__ float wsm[NSPLIT][64];
    __shared__ float linv[64];
    const int t  = threadIdx.x;
    const int bk = blockIdx.x;
    if (t < 64) {
        float mv[NSPLIT];
        float M = -1e30f;
        #pragma unroll
        for (int i = 0; i < NSPLIT; i++) {
            mv[i] = pml[((size_t)(bk*NSPLIT + i)*64 + t)*2 + 0];
            M = fmaxf(M, mv[i]);
        }
        float L = 0.f;
        #pragma unroll
        for (int i = 0; i < NSPLIT; i++) {
            float w = __expf(mv[i] - M);
            wsm[i][t] = w;
            L += w * pml[((size_t)(bk*NSPLIT + i)*64 + t)*2 + 1];
        }
        linv[t] = 1.f / L;
    }
    __syncthreads();
    const int dq   = blockIdx.y*32 + (t & 31);
    const int qrow = t >> 5;
    const int b = bk >> 3, kvh = bk & 7;
    for (int q = qrow; q < 64; q += 8) {
        float o = 0.f;
        #pragma unroll
        for (int i = 0; i < NSPLIT; i++)
            o += po[((size_t)(bk*NSPLIT + i)*64 + q)*128 + dq] * wsm[i][q];
        o *= linv[q];
        int s = q & 15, hh = q >> 4;
        attn_out[(size_t)(b*SEQ + s)*DIM + (kvh*4 + hh)*HD + dq] = o;
    }
}

// ---------------------------------------------------------------------------
extern "C" void kernel_launch(void* const* d_in, const int* in_sizes, int n_in,
                              void* d_out, int out_size)
{
    const float* x     = (const float*)d_in[0];
    const float* mask  = (const float*)d_in[1];
    const float* freqs = (const float*)d_in[2];
    const float* ck    = (const float*)d_in[3];
    const float* cv    = (const float*)d_in[4];
    const float* wq    = (const float*)d_in[5];
    const float* wk    = (const float*)d_in[6];
    const float* wv    = (const float*)d_in[7];
    const float* wo    = (const float*)d_in[8];
    float* out = (float*)d_out;

    float *qkv, *attn, *po, *pml, *pc, *pq;
    cudaGetSymbolAddress((void**)&qkv,  g_qkv);
    cudaGetSymbolAddress((void**)&attn, g_attn);
    cudaGetSymbolAddress((void**)&po,   g_po);
    cudaGetSymbolAddress((void**)&pml,  g_pml);
    cudaGetSymbolAddress((void**)&pc,   g_pc);
    cudaGetSymbolAddress((void**)&pq,   g_pq);

    const int GEMM_SMEM64 = (2*128*ASTR + 2*64*ASTR) * 2;   // 55296
    static int smem_set = 0;
    if (!smem_set) {
        cudaFuncSetAttribute(gemm_mma<64>, cudaFuncAttributeMaxDynamicSharedMemorySize, GEMM_SMEM64);
        cudaFuncSetAttribute(attn_mma, cudaFuncAttributeMaxDynamicSharedMemorySize, ATTN_SMEM);
        smem_set = 1;
    }

    // QKV projection: BN=64, split-K=2 (192 blocks) + rope-fused partial sum
    gemm_mma<64><<<dim3(NQKV/64, 2), 256, GEMM_SMEM64>>>(
        x, wq, wk, wv, pq, NQKV);
    qkv_add_rope<<<NT*NQKV/4/256, 256>>>(pq, qkv, freqs);

    // Attention with fused cache writes + async K/V staging, then combine
    attn_mma<<<dim3(NSPLIT, NKV, BSZ), 256, ATTN_SMEM>>>(
        qkv, ck, cv, out + CK_OFF, out + CV_OFF, mask, po, pml);
    attn_combine<<<dim3(BSZ*NKV, 4), 256>>>(po, pml, attn);

    // Output projection: BN=64, split-K=2 (128 blocks) + partial sum
    gemm_mma<64><<<dim3(DIM/64, 2), 256, GEMM_SMEM64>>>(
        attn, wo, nullptr, nullptr, pc, DIM);
    splitk_add<<<512, 256>>>(pc, out);
}